// round 15
// baseline (speedup 1.0000x reference)
#include <cuda_runtime.h>
#include <cuda_bf16.h>

#define NPTS 4096
#define FEAT 128
#define NEDGE (NPTS - 1)
#define NE 8386560
#define SENTK 0xFFFFFFFFFFFFFFFFULL
#define ECAP 4194304
#define CROUNDS 7
#define DROUNDS 2
#define SHBINS 2048
#define CHUNK 4096
#define NCHUNK 8192
#define NBCAP 33554432u
#define NTILE 32
#define NUPPER 528   // 32*33/2
#define CBUF 2048
#define LDH 72       // bf16 per row per K-stage (64 + 8 pad)
#define LDF 133
#define DSMEM 73728  // 4 * 128*72*2 ; ft (128*133*4=68096) reuses it

#define FLAG_AGG (1ULL << 62)
#define FLAG_PRE (1ULL << 63)

// ---------------- static device scratch ----------------
__device__ __align__(256) float g_D[2][(size_t)NPTS * NPTS];
__device__ float g_sq[2][NPTS];
__device__ int g_capBits[2];
__device__ int g_minDB[2];
__device__ int g_nsamp[2];
__device__ unsigned g_tau[2];
__device__ int g_shist[2][SHBINS];
__device__ unsigned g_ncand[2];
__device__ unsigned g_edges[2 * NEDGE];
__device__ unsigned long long g_best[2][NPTS];
__device__ int g_comp[2][NPTS];
__device__ int g_ncomp[2];
__device__ int g_necnt[2];
__device__ __align__(256) unsigned long long g_elist[2][ECAP];
__device__ float g_dshift;
__device__ unsigned g_base, g_nbins, g_capBin;
__device__ __align__(256) unsigned g_H[2][NBCAP];
__device__ unsigned g_ticket;
__device__ volatile unsigned long long g_flag[NCHUNK];
__device__ double g_dpart[NCHUNK];

// ---------------- init ----------------
__global__ void init_kernel() {
    int t = blockIdx.x * blockDim.x + threadIdx.x;
    if (t < SHBINS) { g_shist[0][t] = 0; g_shist[1][t] = 0; }
    if (t < NPTS) {
        g_comp[0][t] = t; g_comp[1][t] = t;
        g_best[0][t] = SENTK; g_best[1][t] = SENTK;
    }
    if (t == 0) {
        g_capBits[0] = 0; g_capBits[1] = 0;
        g_minDB[0] = 0x7F7FFFFF; g_minDB[1] = 0x7F7FFFFF;
        g_nsamp[0] = 0; g_nsamp[1] = 0;
        g_ncomp[0] = NPTS; g_ncomp[1] = NPTS;
        g_necnt[0] = 0; g_necnt[1] = 0;
        g_ncand[0] = 0; g_ncand[1] = 0;
    }
}

// ---------------- squared norms ----------------
__global__ void sqnorm_kernel(const float* __restrict__ X1, const float* __restrict__ X2) {
    int g = blockIdx.y;
    const float* __restrict__ X = g ? X2 : X1;
    int row = (blockIdx.x * blockDim.x + threadIdx.x) >> 5;
    int lane = threadIdx.x & 31;
    if (row >= NPTS) return;
    float s = 0.f;
#pragma unroll
    for (int c = lane; c < FEAT; c += 32) { float v = X[row * FEAT + c]; s += v * v; }
#pragma unroll
    for (int o = 16; o; o >>= 1) s += __shfl_down_sync(0xffffffffu, s, o);
    if (lane == 0) g_sq[g][row] = s;
}

// ---------------- tensor-core distance matrix (K-staged, upper-tri tiles) ----------------
#define MMA_BF16(c0, c1, c2, c3, a0, a1, a2, a3, b0, b1)                      \
    asm volatile(                                                              \
        "mma.sync.aligned.m16n8k16.row.col.f32.bf16.bf16.f32 "                 \
        "{%0,%1,%2,%3}, {%4,%5,%6,%7}, {%8,%9}, {%0,%1,%2,%3};"                \
        : "+f"(c0), "+f"(c1), "+f"(c2), "+f"(c3)                               \
        : "r"(a0), "r"(a1), "r"(a2), "r"(a3), "r"(b0), "r"(b1))

__global__ void __launch_bounds__(256) dist_kernel(const float* __restrict__ X1,
                                                   const float* __restrict__ X2) {
    int b = blockIdx.x;
    int ti = 0, rem = b;
    while (rem >= NTILE - ti) { rem -= NTILE - ti; ti++; }
    int tj = ti + rem;
    int g = blockIdx.y;
    const float* __restrict__ X = g ? X2 : X1;

    extern __shared__ char sbuf[];
    __nv_bfloat16* Ah = (__nv_bfloat16*)sbuf;               // 128 x 72
    __nv_bfloat16* Al = (__nv_bfloat16*)(sbuf + 18432);
    __nv_bfloat16* Bh = (__nv_bfloat16*)(sbuf + 36864);
    __nv_bfloat16* Bl = (__nv_bfloat16*)(sbuf + 55296);
    float* ft = (float*)sbuf;                               // reuse: 128 x 133
    __shared__ float ssqA[128], ssqB[128], smax[256], sminv[256];

    int tid = threadIdx.x;
    int i0 = ti * 128, j0 = tj * 128;
    if (tid < 128) { ssqA[tid] = g_sq[g][i0 + tid]; ssqB[tid] = g_sq[g][j0 + tid]; }

    int w = tid >> 5, lane = tid & 31;
    int wr = (w >> 2) * 64, wc = (w & 3) * 32;
    int g8 = lane >> 2, tg = lane & 3;

    float acc[4][4][4];
#pragma unroll
    for (int mi = 0; mi < 4; mi++)
#pragma unroll
        for (int ni = 0; ni < 4; ni++)
#pragma unroll
            for (int q = 0; q < 4; q++) acc[mi][ni][q] = 0.f;

    const float4* X4 = (const float4*)X;
#pragma unroll
    for (int s = 0; s < 2; s++) {
        if (s) __syncthreads();   // previous stage's MMA reads complete
        for (int q = tid; q < 2048; q += 256) {
            int r = q >> 4, c4 = q & 15;
            int off = r * LDH + c4 * 4;
            float4 va = X4[(size_t)(i0 + r) * 32 + s * 16 + c4];
            __nv_bfloat162 h01 = __float22bfloat162_rn(make_float2(va.x, va.y));
            __nv_bfloat162 h23 = __float22bfloat162_rn(make_float2(va.z, va.w));
            *(__nv_bfloat162*)&Ah[off] = h01;
            *(__nv_bfloat162*)&Ah[off + 2] = h23;
            *(__nv_bfloat162*)&Al[off] = __float22bfloat162_rn(make_float2(
                va.x - __bfloat162float(h01.x), va.y - __bfloat162float(h01.y)));
            *(__nv_bfloat162*)&Al[off + 2] = __float22bfloat162_rn(make_float2(
                va.z - __bfloat162float(h23.x), va.w - __bfloat162float(h23.y)));
            float4 vb = X4[(size_t)(j0 + r) * 32 + s * 16 + c4];
            __nv_bfloat162 g01 = __float22bfloat162_rn(make_float2(vb.x, vb.y));
            __nv_bfloat162 g23 = __float22bfloat162_rn(make_float2(vb.z, vb.w));
            *(__nv_bfloat162*)&Bh[off] = g01;
            *(__nv_bfloat162*)&Bh[off + 2] = g23;
            *(__nv_bfloat162*)&Bl[off] = __float22bfloat162_rn(make_float2(
                vb.x - __bfloat162float(g01.x), vb.y - __bfloat162float(g01.y)));
            *(__nv_bfloat162*)&Bl[off + 2] = __float22bfloat162_rn(make_float2(
                vb.z - __bfloat162float(g23.x), vb.w - __bfloat162float(g23.y)));
        }
        __syncthreads();
#pragma unroll
        for (int ks = 0; ks < 4; ks++) {
            int kb = ks * 16;
            unsigned ah[4][4], al[4][4];
#pragma unroll
            for (int mi = 0; mi < 4; mi++) {
                int r = wr + mi * 16 + g8;
                int o0 = r * LDH + kb + 2 * tg;
                int o1 = (r + 8) * LDH + kb + 2 * tg;
                ah[mi][0] = *(const unsigned*)&Ah[o0];
                ah[mi][1] = *(const unsigned*)&Ah[o1];
                ah[mi][2] = *(const unsigned*)&Ah[o0 + 8];
                ah[mi][3] = *(const unsigned*)&Ah[o1 + 8];
                al[mi][0] = *(const unsigned*)&Al[o0];
                al[mi][1] = *(const unsigned*)&Al[o1];
                al[mi][2] = *(const unsigned*)&Al[o0 + 8];
                al[mi][3] = *(const unsigned*)&Al[o1 + 8];
            }
#pragma unroll
            for (int ni = 0; ni < 4; ni++) {
                int c = wc + ni * 8 + g8;
                int ob = c * LDH + kb + 2 * tg;
                unsigned bh0 = *(const unsigned*)&Bh[ob];
                unsigned bh1 = *(const unsigned*)&Bh[ob + 8];
                unsigned bl0 = *(const unsigned*)&Bl[ob];
                unsigned bl1 = *(const unsigned*)&Bl[ob + 8];
#pragma unroll
                for (int mi = 0; mi < 4; mi++) {
                    float* a = acc[mi][ni];
                    MMA_BF16(a[0], a[1], a[2], a[3],
                             ah[mi][0], ah[mi][1], ah[mi][2], ah[mi][3], bh0, bh1);
                    MMA_BF16(a[0], a[1], a[2], a[3],
                             al[mi][0], al[mi][1], al[mi][2], al[mi][3], bh0, bh1);
                    MMA_BF16(a[0], a[1], a[2], a[3],
                             ah[mi][0], ah[mi][1], ah[mi][2], ah[mi][3], bl0, bl1);
                }
            }
        }
    }
    __syncthreads();   // done with bf16 smem; ft overwrites

    float lmax = 0.f, lmin = 3.0e38f;
    bool diagBlock = (ti == tj);
#pragma unroll
    for (int mi = 0; mi < 4; mi++) {
#pragma unroll
        for (int ni = 0; ni < 4; ni++) {
            int lr = wr + mi * 16 + g8;
            int lc = wc + ni * 8 + 2 * tg;
            float* a = acc[mi][ni];
#pragma unroll
            for (int q = 0; q < 4; q++) {
                int rr = lr + ((q >> 1) ? 8 : 0);
                int cc = lc + (q & 1);
                float d2 = ssqA[rr] + ssqB[cc] - 2.f * a[q];
                d2 = fmaxf(d2, 0.f);
                float d = (d2 > 1e-12f) ? sqrtf(d2) : 0.f;
                lmax = fmaxf(lmax, d);
                if (!(diagBlock && rr == cc) && d > 0.f) lmin = fminf(lmin, d);
                ft[rr * LDF + cc] = d;
            }
        }
    }
    __syncthreads();

    float* Dg = g_D[g];
    for (int idx = tid; idx < 16384; idx += 256) {
        int r = idx >> 7, c = idx & 127;
        Dg[(size_t)(i0 + r) * NPTS + j0 + c] = ft[r * LDF + c];
    }
    smax[tid] = lmax;
    sminv[tid] = lmin;
    __syncthreads();
    for (int o = 128; o; o >>= 1) {
        if (tid < o) {
            smax[tid] = fmaxf(smax[tid], smax[tid + o]);
            sminv[tid] = fminf(sminv[tid], sminv[tid + o]);
        }
        __syncthreads();
    }
    if (tid == 0) {
        atomicMax(&g_capBits[g], __float_as_int(smax[0]));
        atomicMin(&g_minDB[g], __float_as_int(sminv[0]));
    }
}

// ---------------- sampled histogram (upper-tri remap) ----------------
__global__ void shist_kernel() {
    int g = blockIdx.y;
    __shared__ int h[SHBINS];
    __shared__ int svalid;
    int t = threadIdx.x;
    for (int i = t; i < SHBINS; i += 256) h[i] = 0;
    if (t == 0) svalid = 0;
    __syncthreads();
    unsigned minB = (unsigned)g_minDB[g];
    unsigned long long range = (unsigned long long)((unsigned)g_capBits[g] - minB) + 1;
    const float* __restrict__ D = g_D[g];
    int lval = 0;
#pragma unroll
    for (int s = 0; s < 4; s++) {
        unsigned gid = blockIdx.x * 1024 + t * 4 + s;
        unsigned idx = (gid * 2654435761u) & (unsigned)(NPTS * NPTS - 1);
        int i = (int)(idx >> 12), j = (int)(idx & (NPTS - 1));
        if (i == j) continue;
        int a = min(i, j), bb = max(i, j);
        int db = __float_as_int(D[(size_t)a * NPTS + bb]);
        if (db > 0) {
            int bn = (int)(((unsigned long long)((unsigned)db - minB) * SHBINS) / range);
            atomicAdd(&h[min(bn, SHBINS - 1)], 1);
            lval++;
        }
    }
    atomicAdd(&svalid, lval);
    __syncthreads();
    for (int i = t; i < SHBINS; i += 256)
        if (h[i]) atomicAdd(&g_shist[g][i], h[i]);
    if (t == 0) atomicAdd(&g_nsamp[g], svalid);
}

// ---------------- tau (blocks 0,1) + axis scalars (block 2) ----------------
__global__ void __launch_bounds__(1024) tau_kernel() {
    if (blockIdx.x == 2) {
        if (threadIdx.x) return;
        float cap1 = __int_as_float(g_capBits[0]);
        float cap2 = __int_as_float(g_capBits[1]);
        float dsh = cap1 - cap2;
        g_dshift = dsh;
        unsigned min1 = (unsigned)g_minDB[0];
        float m2 = __int_as_float(g_minDB[1]) + dsh;
        unsigned min2b = (m2 > 0.f) ? __float_as_uint(m2) : 0u;
        unsigned base = min(min1, min2b);
        unsigned max1 = (unsigned)g_capBits[0];
        float c2s = cap2 + dsh;
        unsigned max2b = (c2s > 0.f) ? __float_as_uint(c2s) : 0u;
        unsigned maxa = max(max1, max2b);
        unsigned nb = maxa - base + 2;
        if (nb > NBCAP) { base = maxa - (NBCAP - 2); nb = NBCAP; }
        g_base = base;
        g_nbins = nb;
        unsigned cb = max1 - base;
        g_capBin = min(cb, nb - 1);
        return;
    }
    int g = blockIdx.x;
    __shared__ int h[SHBINS], h2[SHBINS];
    __shared__ int sbin;
    int t = threadIdx.x;
    for (int i = t; i < SHBINS; i += 1024) h[i] = g_shist[g][i];
    if (t == 0) sbin = SHBINS - 1;
    __syncthreads();
    int* cur = h;
    int* nxt = h2;
    for (int off = 1; off < SHBINS; off <<= 1) {
        for (int i = t; i < SHBINS; i += 1024)
            nxt[i] = cur[i] + (i >= off ? cur[i - off] : 0);
        __syncthreads();
        int* tmp = cur; cur = nxt; nxt = tmp;
    }
    int target = g_nsamp[g] / 32;
    for (int i = t; i < SHBINS; i += 1024)
        if (cur[i] >= target && (i == 0 || cur[i - 1] < target)) atomicMin(&sbin, i);
    __syncthreads();
    if (t == 0) {
        unsigned minB = (unsigned)g_minDB[g];
        unsigned long long range = (unsigned long long)((unsigned)g_capBits[g] - minB) + 1;
        g_tau[g] = minB + (unsigned)(((unsigned long long)(sbin + 1) * range) / SHBINS);
    }
}

// ---------------- zero exact histograms + scan flags ----------------
__global__ void zero_kernel() {
    unsigned nb = g_nbins;
    unsigned stride = gridDim.x * blockDim.x;
    unsigned gid = blockIdx.x * blockDim.x + threadIdx.x;
    for (unsigned i = gid; i < nb; i += stride) {
        g_H[0][i] = 0u;
        g_H[1][i] = 0u;
    }
    if (gid < NCHUNK) g_flag[gid] = 0ULL;
    if (gid == 0) g_ticket = 0u;
}

// ---------------- fused: exact histogram + buffered candidate compaction ----------------
__global__ void __launch_bounds__(256) histcand_kernel() {
    int g = blockIdx.y;
    __shared__ unsigned long long buf[CBUF];
    __shared__ unsigned cnt, gbase;
    int t = threadIdx.x;
    if (t == 0) cnt = 0;
    __syncthreads();

    float dsh = g_dshift;
    unsigned tauB = g_tau[g];
    unsigned nb = g_nbins, baseB = g_base;
    size_t blockStart = (size_t)blockIdx.x * 16384;

    for (int it = 0; it < 64; it++) {
        size_t idx = blockStart + (size_t)it * 256 + t;
        int i = (int)(idx >> 12);
        int j = (int)(idx & (NPTS - 1));
        if (j > i) {
            float d = g_D[g][idx];
            unsigned db = __float_as_uint(d);
            float tv = g ? (d + dsh) : d;
            unsigned ab = (tv > 0.f) ? __float_as_uint(tv) : 0u;
            unsigned bi = ab - baseB;
            if (bi > 0x80000000u) bi = 0;
            if (bi >= nb) bi = nb - 1;
            atomicAdd(&g_H[g][bi], 1u);
            if (db < tauB) {
                unsigned p = atomicAdd(&cnt, 1u);
                if (p < CBUF)
                    buf[p] = ((unsigned long long)db << 24) | (unsigned)((i << 12) | j);
            }
        }
        if ((it & 3) == 3 || it == 63) {
            __syncthreads();
            unsigned n = min(cnt, (unsigned)CBUF);
            if (n > CBUF - 1024 || (it == 63 && n > 0)) {
                if (t == 0) gbase = atomicAdd(&g_ncand[g], n);
                __syncthreads();
                unsigned gb = gbase;
                for (unsigned q = t; q < n; q += 256)
                    if (gb + q < ECAP) g_elist[g][gb + q] = buf[q];
                __syncthreads();
                if (t == 0) cnt = 0;
            }
            __syncthreads();
        }
    }
}

// ---------------- compact-list Boruvka scan ----------------
__global__ void __launch_bounds__(256) cmin_kernel() {
    int g = blockIdx.y;
    if (g_ncomp[g] <= 1) return;
    unsigned E = g_ncand[g];
    if (E > ECAP) return;
    const unsigned long long* __restrict__ el = g_elist[g];
    const int* __restrict__ comp = g_comp[g];
    for (unsigned e = blockIdx.x * 256 + threadIdx.x; e < E; e += gridDim.x * 256) {
        unsigned long long k = el[e];
        unsigned eid = (unsigned)(k & 0xFFFFFFu);
        int cu = __ldg(&comp[eid >> 12]), cv = __ldg(&comp[eid & 4095]);
        if (cu != cv) {
            if (k < g_best[g][cu]) atomicMin(&g_best[g][cu], k);
            if (k < g_best[g][cv]) atomicMin(&g_best[g][cv], k);
        }
    }
}

// ---------------- dense Boruvka safety scan (upper-tri D) ----------------
__global__ void __launch_bounds__(256) bmin_kernel() {
    int g = blockIdx.y;
    if (g_ncomp[g] <= 1) return;
    __shared__ int scomp[NPTS];
    int t = threadIdx.x;
    for (int i = t; i < NPTS; i += 256) scomp[i] = g_comp[g][i];
    __syncthreads();
    int warp = t >> 5, lane = t & 31;
    int r = blockIdx.x * 8 + warp;
    int myc = scomp[r];
    const float* __restrict__ D = g_D[g];
    const float* __restrict__ row = D + (size_t)r * NPTS;
    unsigned long long best = SENTK;
    for (int j = lane; j < NPTS; j += 32) {
        if (j == r || scomp[j] == myc) continue;
        float d = (j > r) ? row[j] : D[(size_t)j * NPTS + r];
        int a = min(r, j), bb = max(r, j);
        unsigned long long k =
            ((unsigned long long)__float_as_uint(d) << 24) | (unsigned)((a << 12) | bb);
        if (k < best) best = k;
    }
#pragma unroll
    for (int o = 16; o; o >>= 1) {
        unsigned long long ov = __shfl_down_sync(0xffffffffu, best, o);
        if (ov < best) best = ov;
    }
    if (lane == 0 && best != SENTK) atomicMin(&g_best[g][myc], best);
}

// ---------------- merge components ----------------
__global__ void __launch_bounds__(1024) bmerge_kernel() {
    int g = blockIdx.x;
    if (g_ncomp[g] <= 1) return;
    __shared__ int par[NPTS];
    __shared__ int scnt;
    int t = threadIdx.x;
    for (int i = t; i < NPTS; i += 1024) par[i] = i;
    if (t == 0) scnt = 0;
    __syncthreads();
    for (int v = t; v < NPTS; v += 1024) {
        unsigned long long bk = g_best[g][v];
        if (bk != SENTK) {
            unsigned eid = (unsigned)(bk & 0xFFFFFFu);
            int a = (int)(eid >> 12), b = (int)(eid & 4095);
            int ca = g_comp[g][a], cb = g_comp[g][b];
            int other = (ca == v) ? cb : ca;
            bool add = !(g_best[g][other] == bk && other < v);
            if (add) {
                int slot = atomicAdd(&g_necnt[g], 1);
                if (slot < NEDGE) g_edges[g * NEDGE + slot] = eid;
            }
            par[v] = other;
        }
    }
    __syncthreads();
    for (int v = t; v < NPTS; v += 1024) {
        int p = par[v];
        if (p != v && par[p] == v && v < p) par[v] = v;
    }
    __syncthreads();
    for (int it = 0; it < 13; it++) {
        for (int v = t; v < NPTS; v += 1024) par[v] = par[par[v]];
        __syncthreads();
    }
    for (int i = t; i < NPTS; i += 1024) {
        g_comp[g][i] = par[g_comp[g][i]];
        g_best[g][i] = SENTK;
    }
    __syncthreads();
    int local = 0;
    for (int i = t; i < NPTS; i += 1024)
        if (g_comp[g][i] == i) local++;
    atomicAdd(&scnt, local);
    __syncthreads();
    if (t == 0) g_ncomp[g] = scnt;
}

// ---------------- move tree-edge mass to the cap bin ----------------
__global__ void treefix_kernel() {
    int e = blockIdx.x * blockDim.x + threadIdx.x;
    if (e >= 2 * NEDGE) return;
    int g = e / NEDGE;
    int i = e % NEDGE;
    if (i >= min(g_necnt[g], NEDGE)) return;
    unsigned pk = g_edges[g * NEDGE + i];
    int a = (int)(pk >> 12), b = (int)(pk & 4095);
    float d = g_D[g][(size_t)a * NPTS + b];
    float t = g ? (d + g_dshift) : d;
    unsigned ab = (t > 0.f) ? __float_as_uint(t) : 0u;
    unsigned nb = g_nbins;
    unsigned bi = ab - g_base;
    if (bi > 0x80000000u) bi = 0;
    if (bi >= nb) bi = nb - 1;
    atomicAdd(&g_H[g][bi], (unsigned)-1);
    atomicAdd(&g_H[g][g_capBin], 1u);
}

// ---------------- S3: single-pass decoupled-lookback scan + integration ----------------
__global__ void __launch_bounds__(256) s3_kernel() {
    __shared__ unsigned sbid;
    __shared__ unsigned sh1[CHUNK], sh2[CHUNK];
    __shared__ unsigned ts1[256], ts2[256];
    __shared__ double sred[256];
    __shared__ unsigned soff1, soff2;
    int t = threadIdx.x;
    if (t == 0) sbid = atomicAdd(&g_ticket, 1u);
    __syncthreads();
    unsigned b = sbid;
    unsigned nb = g_nbins;
    unsigned start = b * CHUNK;

    // load chunk (zeros beyond nb)
    for (int i = t; i < CHUNK; i += 256) {
        unsigned id = start + i;
        bool ok = (start < nb) && (id < nb);
        sh1[i] = ok ? g_H[0][id] : 0u;
        sh2[i] = ok ? g_H[1][id] : 0u;
    }
    __syncthreads();
    int b16 = t * 16;
    unsigned a1 = 0, a2 = 0;
#pragma unroll
    for (int k = 0; k < 16; k++) { a1 += sh1[b16 + k]; a2 += sh2[b16 + k]; }
    ts1[t] = a1; ts2[t] = a2;
    __syncthreads();
    for (int off = 1; off < 256; off <<= 1) {
        unsigned b1 = (t >= off) ? ts1[t - off] : 0u;
        unsigned b2 = (t >= off) ? ts2[t - off] : 0u;
        __syncthreads();
        ts1[t] += b1; ts2[t] += b2;
        __syncthreads();
    }
    unsigned tot1 = ts1[255], tot2 = ts2[255];

    // lookback (thread 0)
    if (t == 0) {
        unsigned long long packA =
            FLAG_AGG | (unsigned long long)(tot1 & 0xFFFFFFu) |
            ((unsigned long long)(tot2 & 0xFFFFFFu) << 24);
        if (b == 0) {
            soff1 = 0; soff2 = 0;
            atomicExch((unsigned long long*)&g_flag[0], packA | FLAG_PRE);
        } else {
            atomicExch((unsigned long long*)&g_flag[b], packA);
            unsigned r1 = 0, r2 = 0;
            int idx = (int)b - 1;
            while (idx >= 0) {
                unsigned long long v = g_flag[idx];
                if (!(v & (FLAG_AGG | FLAG_PRE))) continue;   // spin
                r1 += (unsigned)(v & 0xFFFFFFu);
                r2 += (unsigned)((v >> 24) & 0xFFFFFFu);
                if (v & FLAG_PRE) break;
                idx--;
            }
            soff1 = r1; soff2 = r2;
            unsigned long long packP =
                FLAG_PRE | FLAG_AGG |
                (unsigned long long)((r1 + tot1) & 0xFFFFFFu) |
                ((unsigned long long)((r2 + tot2) & 0xFFFFFFu) << 24);
            atomicExch((unsigned long long*)&g_flag[b], packP);
        }
    }
    __syncthreads();

    if (start >= nb) { if (t == 0) g_dpart[b] = 0.0; return; }

    unsigned c1 = soff1 + ts1[t] - a1;
    unsigned c2 = soff2 + ts2[t] - a2;
    unsigned baseBits = g_base;
    double acc = 0.0;
#pragma unroll
    for (int k = 0; k < 16; k++) {
        unsigned id = start + b16 + k;
        if (id < nb) {
            c1 += sh1[b16 + k]; c2 += sh2[b16 + k];
            float t0 = __uint_as_float(baseBits + id);
            float t1 = __uint_as_float(baseBits + id + 1);
            int df = (int)(c1 - c2);
            acc += fabs((double)df) * (double)(t1 - t0);
        }
    }
    sred[t] = acc;
    __syncthreads();
    for (int o = 128; o; o >>= 1) {
        if (t < o) sred[t] += sred[t + o];
        __syncthreads();
    }
    if (t == 0) g_dpart[b] = sred[0];
}

// ---------------- S4: final reduce ----------------
__global__ void __launch_bounds__(1024) s4_kernel(float* __restrict__ out) {
    __shared__ double sh[1024];
    int t = threadIdx.x;
    double a = 0.0;
    for (int i = t; i < NCHUNK; i += 1024) a += g_dpart[i];
    sh[t] = a;
    __syncthreads();
    for (int o = 512; o; o >>= 1) {
        if (t < o) sh[t] += sh[t + o];
        __syncthreads();
    }
    if (t == 0) out[0] = (float)sh[0];
}

// ---------------- launch ----------------
extern "C" void kernel_launch(void* const* d_in, const int* in_sizes, int n_in,
                              void* d_out, int out_size) {
    const float* X1 = (const float*)d_in[0];
    const float* X2 = (const float*)d_in[2];
    float* out = (float*)d_out;

    cudaFuncSetAttribute(dist_kernel, cudaFuncAttributeMaxDynamicSharedMemorySize, DSMEM);

    init_kernel<<<16, 256>>>();
    sqnorm_kernel<<<dim3(NPTS / 8, 2), 256>>>(X1, X2);
    dist_kernel<<<dim3(NUPPER, 2), 256, DSMEM>>>(X1, X2);
    shist_kernel<<<dim3(64, 2), 256>>>();
    tau_kernel<<<3, 1024>>>();
    zero_kernel<<<2048, 256>>>();
    histcand_kernel<<<dim3(1024, 2), 256>>>();

    for (int r = 0; r < CROUNDS; r++) {
        cmin_kernel<<<dim3(64, 2), 256>>>();
        bmerge_kernel<<<2, 1024>>>();
    }
    for (int r = 0; r < DROUNDS; r++) {
        bmin_kernel<<<dim3(NPTS / 8, 2), 256>>>();
        bmerge_kernel<<<2, 1024>>>();
    }

    treefix_kernel<<<(2 * NEDGE + 255) / 256, 256>>>();
    s3_kernel<<<NCHUNK, 256>>>();
    s4_kernel<<<1, 1024>>>(out);
}

// round 16
// speedup vs baseline: 1.2154x; 1.2154x over previous
#include <cuda_runtime.h>
#include <cuda_bf16.h>

#define NPTS 4096
#define FEAT 128
#define NEDGE (NPTS - 1)
#define NE 8386560
#define SENTK 0xFFFFFFFFFFFFFFFFULL
#define ECAP 4194304
#define CROUNDS 7
#define DROUNDS 2
#define SHBINS 2048
#define CHUNK 4096
#define NCHUNK 8192
#define NBCAP 33554432u
#define NTILE 32
#define NUPPER 528   // 32*33/2
#define CBUF 2048
#define LDH 72       // bf16 per row per K-stage (64 + 8 pad)
#define LDF 133
#define DSMEM 73728  // 4 * 128*72*2 ; ft (128*133*4=68096) reuses it

// ---------------- static device scratch ----------------
__device__ __align__(256) float g_D[2][(size_t)NPTS * NPTS];
__device__ float g_sq[2][NPTS];
__device__ int g_capBits[2];
__device__ int g_minDB[2];
__device__ int g_nsamp[2];
__device__ unsigned g_tau[2];
__device__ int g_shist[2][SHBINS];
__device__ unsigned g_ncand[2];
__device__ unsigned g_edges[2 * NEDGE];
__device__ unsigned long long g_best[2][NPTS];
__device__ int g_comp[2][NPTS];
__device__ int g_ncomp[2];
__device__ int g_necnt[2];
__device__ __align__(256) unsigned long long g_elist[2][ECAP];
__device__ float g_dshift;
__device__ unsigned g_base, g_nbins, g_capBin;
__device__ __align__(256) unsigned g_H[2][NBCAP];
__device__ unsigned g_p1[NCHUNK], g_p2[NCHUNK];
__device__ unsigned g_off1[NCHUNK], g_off2[NCHUNK];
__device__ double g_dpart[NCHUNK];

// ---------------- init ----------------
__global__ void init_kernel() {
    int t = blockIdx.x * blockDim.x + threadIdx.x;
    if (t < SHBINS) { g_shist[0][t] = 0; g_shist[1][t] = 0; }
    if (t < NPTS) {
        g_comp[0][t] = t; g_comp[1][t] = t;
        g_best[0][t] = SENTK; g_best[1][t] = SENTK;
    }
    if (t == 0) {
        g_capBits[0] = 0; g_capBits[1] = 0;
        g_minDB[0] = 0x7F7FFFFF; g_minDB[1] = 0x7F7FFFFF;
        g_nsamp[0] = 0; g_nsamp[1] = 0;
        g_ncomp[0] = NPTS; g_ncomp[1] = NPTS;
        g_necnt[0] = 0; g_necnt[1] = 0;
        g_ncand[0] = 0; g_ncand[1] = 0;
    }
}

// ---------------- squared norms ----------------
__global__ void sqnorm_kernel(const float* __restrict__ X1, const float* __restrict__ X2) {
    int g = blockIdx.y;
    const float* __restrict__ X = g ? X2 : X1;
    int row = (blockIdx.x * blockDim.x + threadIdx.x) >> 5;
    int lane = threadIdx.x & 31;
    if (row >= NPTS) return;
    float s = 0.f;
#pragma unroll
    for (int c = lane; c < FEAT; c += 32) { float v = X[row * FEAT + c]; s += v * v; }
#pragma unroll
    for (int o = 16; o; o >>= 1) s += __shfl_down_sync(0xffffffffu, s, o);
    if (lane == 0) g_sq[g][row] = s;
}

// ---------------- tensor-core distance matrix (K-staged, upper-tri tiles) ----------------
#define MMA_BF16(c0, c1, c2, c3, a0, a1, a2, a3, b0, b1)                      \
    asm volatile(                                                              \
        "mma.sync.aligned.m16n8k16.row.col.f32.bf16.bf16.f32 "                 \
        "{%0,%1,%2,%3}, {%4,%5,%6,%7}, {%8,%9}, {%0,%1,%2,%3};"                \
        : "+f"(c0), "+f"(c1), "+f"(c2), "+f"(c3)                               \
        : "r"(a0), "r"(a1), "r"(a2), "r"(a3), "r"(b0), "r"(b1))

__global__ void __launch_bounds__(256) dist_kernel(const float* __restrict__ X1,
                                                   const float* __restrict__ X2) {
    int b = blockIdx.x;
    int ti = 0, rem = b;
    while (rem >= NTILE - ti) { rem -= NTILE - ti; ti++; }
    int tj = ti + rem;
    int g = blockIdx.y;
    const float* __restrict__ X = g ? X2 : X1;

    extern __shared__ char sbuf[];
    __nv_bfloat16* Ah = (__nv_bfloat16*)sbuf;               // 128 x 72
    __nv_bfloat16* Al = (__nv_bfloat16*)(sbuf + 18432);
    __nv_bfloat16* Bh = (__nv_bfloat16*)(sbuf + 36864);
    __nv_bfloat16* Bl = (__nv_bfloat16*)(sbuf + 55296);
    float* ft = (float*)sbuf;                               // reuse: 128 x 133
    __shared__ float ssqA[128], ssqB[128], smax[256], sminv[256];

    int tid = threadIdx.x;
    int i0 = ti * 128, j0 = tj * 128;
    if (tid < 128) { ssqA[tid] = g_sq[g][i0 + tid]; ssqB[tid] = g_sq[g][j0 + tid]; }

    int w = tid >> 5, lane = tid & 31;
    int wr = (w >> 2) * 64, wc = (w & 3) * 32;
    int g8 = lane >> 2, tg = lane & 3;

    float acc[4][4][4];
#pragma unroll
    for (int mi = 0; mi < 4; mi++)
#pragma unroll
        for (int ni = 0; ni < 4; ni++)
#pragma unroll
            for (int q = 0; q < 4; q++) acc[mi][ni][q] = 0.f;

    const float4* X4 = (const float4*)X;
#pragma unroll
    for (int s = 0; s < 2; s++) {
        if (s) __syncthreads();   // previous stage's MMA reads complete
        for (int q = tid; q < 2048; q += 256) {
            int r = q >> 4, c4 = q & 15;
            int off = r * LDH + c4 * 4;
            float4 va = X4[(size_t)(i0 + r) * 32 + s * 16 + c4];
            __nv_bfloat162 h01 = __float22bfloat162_rn(make_float2(va.x, va.y));
            __nv_bfloat162 h23 = __float22bfloat162_rn(make_float2(va.z, va.w));
            *(__nv_bfloat162*)&Ah[off] = h01;
            *(__nv_bfloat162*)&Ah[off + 2] = h23;
            *(__nv_bfloat162*)&Al[off] = __float22bfloat162_rn(make_float2(
                va.x - __bfloat162float(h01.x), va.y - __bfloat162float(h01.y)));
            *(__nv_bfloat162*)&Al[off + 2] = __float22bfloat162_rn(make_float2(
                va.z - __bfloat162float(h23.x), va.w - __bfloat162float(h23.y)));
            float4 vb = X4[(size_t)(j0 + r) * 32 + s * 16 + c4];
            __nv_bfloat162 g01 = __float22bfloat162_rn(make_float2(vb.x, vb.y));
            __nv_bfloat162 g23 = __float22bfloat162_rn(make_float2(vb.z, vb.w));
            *(__nv_bfloat162*)&Bh[off] = g01;
            *(__nv_bfloat162*)&Bh[off + 2] = g23;
            *(__nv_bfloat162*)&Bl[off] = __float22bfloat162_rn(make_float2(
                vb.x - __bfloat162float(g01.x), vb.y - __bfloat162float(g01.y)));
            *(__nv_bfloat162*)&Bl[off + 2] = __float22bfloat162_rn(make_float2(
                vb.z - __bfloat162float(g23.x), vb.w - __bfloat162float(g23.y)));
        }
        __syncthreads();
#pragma unroll
        for (int ks = 0; ks < 4; ks++) {
            int kb = ks * 16;
            unsigned ah[4][4], al[4][4];
#pragma unroll
            for (int mi = 0; mi < 4; mi++) {
                int r = wr + mi * 16 + g8;
                int o0 = r * LDH + kb + 2 * tg;
                int o1 = (r + 8) * LDH + kb + 2 * tg;
                ah[mi][0] = *(const unsigned*)&Ah[o0];
                ah[mi][1] = *(const unsigned*)&Ah[o1];
                ah[mi][2] = *(const unsigned*)&Ah[o0 + 8];
                ah[mi][3] = *(const unsigned*)&Ah[o1 + 8];
                al[mi][0] = *(const unsigned*)&Al[o0];
                al[mi][1] = *(const unsigned*)&Al[o1];
                al[mi][2] = *(const unsigned*)&Al[o0 + 8];
                al[mi][3] = *(const unsigned*)&Al[o1 + 8];
            }
#pragma unroll
            for (int ni = 0; ni < 4; ni++) {
                int c = wc + ni * 8 + g8;
                int ob = c * LDH + kb + 2 * tg;
                unsigned bh0 = *(const unsigned*)&Bh[ob];
                unsigned bh1 = *(const unsigned*)&Bh[ob + 8];
                unsigned bl0 = *(const unsigned*)&Bl[ob];
                unsigned bl1 = *(const unsigned*)&Bl[ob + 8];
#pragma unroll
                for (int mi = 0; mi < 4; mi++) {
                    float* a = acc[mi][ni];
                    MMA_BF16(a[0], a[1], a[2], a[3],
                             ah[mi][0], ah[mi][1], ah[mi][2], ah[mi][3], bh0, bh1);
                    MMA_BF16(a[0], a[1], a[2], a[3],
                             al[mi][0], al[mi][1], al[mi][2], al[mi][3], bh0, bh1);
                    MMA_BF16(a[0], a[1], a[2], a[3],
                             ah[mi][0], ah[mi][1], ah[mi][2], ah[mi][3], bl0, bl1);
                }
            }
        }
    }
    __syncthreads();   // done with bf16 smem; ft overwrites

    float lmax = 0.f, lmin = 3.0e38f;
    bool diagBlock = (ti == tj);
#pragma unroll
    for (int mi = 0; mi < 4; mi++) {
#pragma unroll
        for (int ni = 0; ni < 4; ni++) {
            int lr = wr + mi * 16 + g8;
            int lc = wc + ni * 8 + 2 * tg;
            float* a = acc[mi][ni];
#pragma unroll
            for (int q = 0; q < 4; q++) {
                int rr = lr + ((q >> 1) ? 8 : 0);
                int cc = lc + (q & 1);
                float d2 = ssqA[rr] + ssqB[cc] - 2.f * a[q];
                d2 = fmaxf(d2, 0.f);
                float d = (d2 > 1e-12f) ? sqrtf(d2) : 0.f;
                lmax = fmaxf(lmax, d);
                if (!(diagBlock && rr == cc) && d > 0.f) lmin = fminf(lmin, d);
                ft[rr * LDF + cc] = d;
            }
        }
    }
    __syncthreads();

    float* Dg = g_D[g];
    for (int idx = tid; idx < 16384; idx += 256) {
        int r = idx >> 7, c = idx & 127;
        Dg[(size_t)(i0 + r) * NPTS + j0 + c] = ft[r * LDF + c];
    }
    smax[tid] = lmax;
    sminv[tid] = lmin;
    __syncthreads();
    for (int o = 128; o; o >>= 1) {
        if (tid < o) {
            smax[tid] = fmaxf(smax[tid], smax[tid + o]);
            sminv[tid] = fminf(sminv[tid], sminv[tid + o]);
        }
        __syncthreads();
    }
    if (tid == 0) {
        atomicMax(&g_capBits[g], __float_as_int(smax[0]));
        atomicMin(&g_minDB[g], __float_as_int(sminv[0]));
    }
}

// ---------------- sampled histogram (upper-tri remap) ----------------
__global__ void shist_kernel() {
    int g = blockIdx.y;
    __shared__ int h[SHBINS];
    __shared__ int svalid;
    int t = threadIdx.x;
    for (int i = t; i < SHBINS; i += 256) h[i] = 0;
    if (t == 0) svalid = 0;
    __syncthreads();
    unsigned minB = (unsigned)g_minDB[g];
    unsigned long long range = (unsigned long long)((unsigned)g_capBits[g] - minB) + 1;
    const float* __restrict__ D = g_D[g];
    int lval = 0;
#pragma unroll
    for (int s = 0; s < 4; s++) {
        unsigned gid = blockIdx.x * 1024 + t * 4 + s;
        unsigned idx = (gid * 2654435761u) & (unsigned)(NPTS * NPTS - 1);
        int i = (int)(idx >> 12), j = (int)(idx & (NPTS - 1));
        if (i == j) continue;
        int a = min(i, j), bb = max(i, j);
        int db = __float_as_int(D[(size_t)a * NPTS + bb]);
        if (db > 0) {
            int bn = (int)(((unsigned long long)((unsigned)db - minB) * SHBINS) / range);
            atomicAdd(&h[min(bn, SHBINS - 1)], 1);
            lval++;
        }
    }
    atomicAdd(&svalid, lval);
    __syncthreads();
    for (int i = t; i < SHBINS; i += 256)
        if (h[i]) atomicAdd(&g_shist[g][i], h[i]);
    if (t == 0) atomicAdd(&g_nsamp[g], svalid);
}

// ---------------- tau (blocks 0,1) + axis scalars (block 2) ----------------
__global__ void __launch_bounds__(1024) tau_kernel() {
    if (blockIdx.x == 2) {
        if (threadIdx.x) return;
        float cap1 = __int_as_float(g_capBits[0]);
        float cap2 = __int_as_float(g_capBits[1]);
        float dsh = cap1 - cap2;
        g_dshift = dsh;
        unsigned min1 = (unsigned)g_minDB[0];
        float m2 = __int_as_float(g_minDB[1]) + dsh;
        unsigned min2b = (m2 > 0.f) ? __float_as_uint(m2) : 0u;
        unsigned base = min(min1, min2b);
        unsigned max1 = (unsigned)g_capBits[0];
        float c2s = cap2 + dsh;
        unsigned max2b = (c2s > 0.f) ? __float_as_uint(c2s) : 0u;
        unsigned maxa = max(max1, max2b);
        unsigned nb = maxa - base + 2;
        if (nb > NBCAP) { base = maxa - (NBCAP - 2); nb = NBCAP; }
        g_base = base;
        g_nbins = nb;
        unsigned cb = max1 - base;
        g_capBin = min(cb, nb - 1);
        return;
    }
    int g = blockIdx.x;
    __shared__ int h[SHBINS], h2[SHBINS];
    __shared__ int sbin;
    int t = threadIdx.x;
    for (int i = t; i < SHBINS; i += 1024) h[i] = g_shist[g][i];
    if (t == 0) sbin = SHBINS - 1;
    __syncthreads();
    int* cur = h;
    int* nxt = h2;
    for (int off = 1; off < SHBINS; off <<= 1) {
        for (int i = t; i < SHBINS; i += 1024)
            nxt[i] = cur[i] + (i >= off ? cur[i - off] : 0);
        __syncthreads();
        int* tmp = cur; cur = nxt; nxt = tmp;
    }
    int target = g_nsamp[g] / 32;
    for (int i = t; i < SHBINS; i += 1024)
        if (cur[i] >= target && (i == 0 || cur[i - 1] < target)) atomicMin(&sbin, i);
    __syncthreads();
    if (t == 0) {
        unsigned minB = (unsigned)g_minDB[g];
        unsigned long long range = (unsigned long long)((unsigned)g_capBits[g] - minB) + 1;
        g_tau[g] = minB + (unsigned)(((unsigned long long)(sbin + 1) * range) / SHBINS);
    }
}

// ---------------- zero exact histograms ----------------
__global__ void zero_kernel() {
    unsigned nb = g_nbins;
    unsigned stride = gridDim.x * blockDim.x;
    for (unsigned i = blockIdx.x * blockDim.x + threadIdx.x; i < nb; i += stride) {
        g_H[0][i] = 0u;
        g_H[1][i] = 0u;
    }
}

// ---------------- fused: exact histogram + buffered candidate compaction ----------------
__global__ void __launch_bounds__(256) histcand_kernel() {
    int g = blockIdx.y;
    __shared__ unsigned long long buf[CBUF];
    __shared__ unsigned cnt, gbase;
    int t = threadIdx.x;
    if (t == 0) cnt = 0;
    __syncthreads();

    float dsh = g_dshift;
    unsigned tauB = g_tau[g];
    unsigned nb = g_nbins, baseB = g_base;
    size_t blockStart = (size_t)blockIdx.x * 16384;

    for (int it = 0; it < 64; it++) {
        size_t idx = blockStart + (size_t)it * 256 + t;
        int i = (int)(idx >> 12);
        int j = (int)(idx & (NPTS - 1));
        if (j > i) {
            float d = g_D[g][idx];
            unsigned db = __float_as_uint(d);
            float tv = g ? (d + dsh) : d;
            unsigned ab = (tv > 0.f) ? __float_as_uint(tv) : 0u;
            unsigned bi = ab - baseB;
            if (bi > 0x80000000u) bi = 0;
            if (bi >= nb) bi = nb - 1;
            atomicAdd(&g_H[g][bi], 1u);
            if (db < tauB) {
                unsigned p = atomicAdd(&cnt, 1u);
                if (p < CBUF)
                    buf[p] = ((unsigned long long)db << 24) | (unsigned)((i << 12) | j);
            }
        }
        if ((it & 3) == 3 || it == 63) {
            __syncthreads();
            unsigned n = min(cnt, (unsigned)CBUF);
            if (n > CBUF - 1024 || (it == 63 && n > 0)) {
                if (t == 0) gbase = atomicAdd(&g_ncand[g], n);
                __syncthreads();
                unsigned gb = gbase;
                for (unsigned q = t; q < n; q += 256)
                    if (gb + q < ECAP) g_elist[g][gb + q] = buf[q];
                __syncthreads();
                if (t == 0) cnt = 0;
            }
            __syncthreads();
        }
    }
}

// ---------------- compact-list Boruvka scan ----------------
__global__ void __launch_bounds__(256) cmin_kernel() {
    int g = blockIdx.y;
    if (g_ncomp[g] <= 1) return;
    unsigned E = g_ncand[g];
    if (E > ECAP) return;
    const unsigned long long* __restrict__ el = g_elist[g];
    const int* __restrict__ comp = g_comp[g];
    for (unsigned e = blockIdx.x * 256 + threadIdx.x; e < E; e += gridDim.x * 256) {
        unsigned long long k = el[e];
        unsigned eid = (unsigned)(k & 0xFFFFFFu);
        int cu = __ldg(&comp[eid >> 12]), cv = __ldg(&comp[eid & 4095]);
        if (cu != cv) {
            if (k < g_best[g][cu]) atomicMin(&g_best[g][cu], k);
            if (k < g_best[g][cv]) atomicMin(&g_best[g][cv], k);
        }
    }
}

// ---------------- dense Boruvka safety scan (upper-tri D) ----------------
__global__ void __launch_bounds__(256) bmin_kernel() {
    int g = blockIdx.y;
    if (g_ncomp[g] <= 1) return;
    __shared__ int scomp[NPTS];
    int t = threadIdx.x;
    for (int i = t; i < NPTS; i += 256) scomp[i] = g_comp[g][i];
    __syncthreads();
    int warp = t >> 5, lane = t & 31;
    int r = blockIdx.x * 8 + warp;
    int myc = scomp[r];
    const float* __restrict__ D = g_D[g];
    const float* __restrict__ row = D + (size_t)r * NPTS;
    unsigned long long best = SENTK;
    for (int j = lane; j < NPTS; j += 32) {
        if (j == r || scomp[j] == myc) continue;
        float d = (j > r) ? row[j] : D[(size_t)j * NPTS + r];
        int a = min(r, j), bb = max(r, j);
        unsigned long long k =
            ((unsigned long long)__float_as_uint(d) << 24) | (unsigned)((a << 12) | bb);
        if (k < best) best = k;
    }
#pragma unroll
    for (int o = 16; o; o >>= 1) {
        unsigned long long ov = __shfl_down_sync(0xffffffffu, best, o);
        if (ov < best) best = ov;
    }
    if (lane == 0 && best != SENTK) atomicMin(&g_best[g][myc], best);
}

// ---------------- merge components ----------------
__global__ void __launch_bounds__(1024) bmerge_kernel() {
    int g = blockIdx.x;
    if (g_ncomp[g] <= 1) return;
    __shared__ int par[NPTS];
    __shared__ int scnt;
    int t = threadIdx.x;
    for (int i = t; i < NPTS; i += 1024) par[i] = i;
    if (t == 0) scnt = 0;
    __syncthreads();
    for (int v = t; v < NPTS; v += 1024) {
        unsigned long long bk = g_best[g][v];
        if (bk != SENTK) {
            unsigned eid = (unsigned)(bk & 0xFFFFFFu);
            int a = (int)(eid >> 12), b = (int)(eid & 4095);
            int ca = g_comp[g][a], cb = g_comp[g][b];
            int other = (ca == v) ? cb : ca;
            bool add = !(g_best[g][other] == bk && other < v);
            if (add) {
                int slot = atomicAdd(&g_necnt[g], 1);
                if (slot < NEDGE) g_edges[g * NEDGE + slot] = eid;
            }
            par[v] = other;
        }
    }
    __syncthreads();
    for (int v = t; v < NPTS; v += 1024) {
        int p = par[v];
        if (p != v && par[p] == v && v < p) par[v] = v;
    }
    __syncthreads();
    for (int it = 0; it < 13; it++) {
        for (int v = t; v < NPTS; v += 1024) par[v] = par[par[v]];
        __syncthreads();
    }
    for (int i = t; i < NPTS; i += 1024) {
        g_comp[g][i] = par[g_comp[g][i]];
        g_best[g][i] = SENTK;
    }
    __syncthreads();
    int local = 0;
    for (int i = t; i < NPTS; i += 1024)
        if (g_comp[g][i] == i) local++;
    atomicAdd(&scnt, local);
    __syncthreads();
    if (t == 0) g_ncomp[g] = scnt;
}

// ---------------- move tree-edge mass to the cap bin ----------------
__global__ void treefix_kernel() {
    int e = blockIdx.x * blockDim.x + threadIdx.x;
    if (e >= 2 * NEDGE) return;
    int g = e / NEDGE;
    int i = e % NEDGE;
    if (i >= min(g_necnt[g], NEDGE)) return;
    unsigned pk = g_edges[g * NEDGE + i];
    int a = (int)(pk >> 12), b = (int)(pk & 4095);
    float d = g_D[g][(size_t)a * NPTS + b];
    float t = g ? (d + g_dshift) : d;
    unsigned ab = (t > 0.f) ? __float_as_uint(t) : 0u;
    unsigned nb = g_nbins;
    unsigned bi = ab - g_base;
    if (bi > 0x80000000u) bi = 0;
    if (bi >= nb) bi = nb - 1;
    atomicAdd(&g_H[g][bi], (unsigned)-1);
    atomicAdd(&g_H[g][g_capBin], 1u);
}

// ---------------- S1: per-chunk sums ----------------
__global__ void __launch_bounds__(256) s1_kernel() {
    int b = blockIdx.x;
    unsigned nb = g_nbins;
    unsigned start = (unsigned)b * CHUNK;
    int t = threadIdx.x;
    __shared__ unsigned r1[256], r2[256];
    unsigned a1 = 0, a2 = 0;
    if (start < nb) {
        for (int i = t; i < CHUNK; i += 256) {
            unsigned id = start + i;
            if (id < nb) { a1 += g_H[0][id]; a2 += g_H[1][id]; }
        }
    }
    r1[t] = a1; r2[t] = a2;
    __syncthreads();
    for (int o = 128; o; o >>= 1) {
        if (t < o) { r1[t] += r1[t + o]; r2[t] += r2[t + o]; }
        __syncthreads();
    }
    if (t == 0) { g_p1[b] = r1[0]; g_p2[b] = r2[0]; }
}

// ---------------- S2: exclusive scan of chunk sums ----------------
__global__ void __launch_bounds__(1024) s2_kernel() {
    __shared__ unsigned sh1[1024], sh2[1024];
    int t = threadIdx.x;
    unsigned l1[8], l2[8], a1 = 0, a2 = 0;
#pragma unroll
    for (int k = 0; k < 8; k++) {
        int i = t * 8 + k;
        l1[k] = g_p1[i]; l2[k] = g_p2[i];
        a1 += l1[k]; a2 += l2[k];
    }
    sh1[t] = a1; sh2[t] = a2;
    __syncthreads();
    for (int off = 1; off < 1024; off <<= 1) {
        unsigned b1 = (t >= off) ? sh1[t - off] : 0u;
        unsigned b2 = (t >= off) ? sh2[t - off] : 0u;
        __syncthreads();
        sh1[t] += b1; sh2[t] += b2;
        __syncthreads();
    }
    unsigned r1 = sh1[t] - a1, r2 = sh2[t] - a2;
#pragma unroll
    for (int k = 0; k < 8; k++) {
        int i = t * 8 + k;
        g_off1[i] = r1; g_off2[i] = r2;
        r1 += l1[k]; r2 += l2[k];
    }
}

// ---------------- S3: intra-chunk scan + |F1-F2|*dt integration ----------------
__global__ void __launch_bounds__(256) s3_kernel() {
    int b = blockIdx.x;
    unsigned nb = g_nbins;
    unsigned start = (unsigned)b * CHUNK;
    int t = threadIdx.x;
    if (start >= nb) { if (t == 0) g_dpart[b] = 0.0; return; }
    __shared__ unsigned sh1[CHUNK], sh2[CHUNK];
    __shared__ unsigned ts1[256], ts2[256];
    __shared__ double sred[256];
    for (int i = t; i < CHUNK; i += 256) {
        unsigned id = start + i;
        bool ok = id < nb;
        sh1[i] = ok ? g_H[0][id] : 0u;
        sh2[i] = ok ? g_H[1][id] : 0u;
    }
    __syncthreads();
    int b16 = t * 16;
    unsigned a1 = 0, a2 = 0;
#pragma unroll
    for (int k = 0; k < 16; k++) { a1 += sh1[b16 + k]; a2 += sh2[b16 + k]; }
    ts1[t] = a1; ts2[t] = a2;
    __syncthreads();
    for (int off = 1; off < 256; off <<= 1) {
        unsigned b1 = (t >= off) ? ts1[t - off] : 0u;
        unsigned b2 = (t >= off) ? ts2[t - off] : 0u;
        __syncthreads();
        ts1[t] += b1; ts2[t] += b2;
        __syncthreads();
    }
    unsigned c1 = g_off1[b] + ts1[t] - a1;
    unsigned c2 = g_off2[b] + ts2[t] - a2;
    unsigned baseBits = g_base;
    double acc = 0.0;
#pragma unroll
    for (int k = 0; k < 16; k++) {
        unsigned id = start + b16 + k;
        if (id < nb) {
            c1 += sh1[b16 + k]; c2 += sh2[b16 + k];
            float t0 = __uint_as_float(baseBits + id);
            float t1 = __uint_as_float(baseBits + id + 1);
            int df = (int)(c1 - c2);
            acc += fabs((double)df) * (double)(t1 - t0);
        }
    }
    sred[t] = acc;
    __syncthreads();
    for (int o = 128; o; o >>= 1) {
        if (t < o) sred[t] += sred[t + o];
        __syncthreads();
    }
    if (t == 0) g_dpart[b] = sred[0];
}

// ---------------- S4: final reduce ----------------
__global__ void __launch_bounds__(1024) s4_kernel(float* __restrict__ out) {
    __shared__ double sh[1024];
    int t = threadIdx.x;
    double a = 0.0;
    for (int i = t; i < NCHUNK; i += 1024) a += g_dpart[i];
    sh[t] = a;
    __syncthreads();
    for (int o = 512; o; o >>= 1) {
        if (t < o) sh[t] += sh[t + o];
        __syncthreads();
    }
    if (t == 0) out[0] = (float)sh[0];
}

// ---------------- launch ----------------
extern "C" void kernel_launch(void* const* d_in, const int* in_sizes, int n_in,
                              void* d_out, int out_size) {
    const float* X1 = (const float*)d_in[0];
    const float* X2 = (const float*)d_in[2];
    float* out = (float*)d_out;

    cudaFuncSetAttribute(dist_kernel, cudaFuncAttributeMaxDynamicSharedMemorySize, DSMEM);

    init_kernel<<<16, 256>>>();
    sqnorm_kernel<<<dim3(NPTS / 8, 2), 256>>>(X1, X2);
    dist_kernel<<<dim3(NUPPER, 2), 256, DSMEM>>>(X1, X2);
    shist_kernel<<<dim3(64, 2), 256>>>();
    tau_kernel<<<3, 1024>>>();
    zero_kernel<<<2048, 256>>>();
    histcand_kernel<<<dim3(1024, 2), 256>>>();

    for (int r = 0; r < CROUNDS; r++) {
        cmin_kernel<<<dim3(64, 2), 256>>>();
        bmerge_kernel<<<2, 1024>>>();
    }
    for (int r = 0; r < DROUNDS; r++) {
        bmin_kernel<<<dim3(NPTS / 8, 2), 256>>>();
        bmerge_kernel<<<2, 1024>>>();
    }

    treefix_kernel<<<(2 * NEDGE + 255) / 256, 256>>>();
    s1_kernel<<<NCHUNK, 256>>>();
    s2_kernel<<<1, 1024>>>();
    s3_kernel<<<NCHUNK, 256>>>();
    s4_kernel<<<1, 1024>>>(out);
}